// round 2
// baseline (speedup 1.0000x reference)
#include <cuda_runtime.h>
#include <cstdint>

#define N_NODES 100000
#define N_EDGES 1600000
#define DIM 64
#define N_GRAPHS 2048
#define BN_EPS 1e-5f
#define NEG 0.01f

typedef unsigned long long ull;

// ---------------- scratch (device globals; no allocation allowed) ----------
__device__ float g_h1[N_NODES * DIM];
__device__ float g_h2[N_NODES * DIM];
__device__ float g_h3[N_NODES * DIM];
__device__ float g_agg[N_NODES * DIM];
__device__ float g_pool[N_GRAPHS * DIM];

// ---------------- f32x2 helpers (sm_100: 3-reg FFMA is half rate; FFMA2 is full) ----
__device__ __forceinline__ ull ffma2(ull a, ull b, ull c) {
    ull d;
    asm("fma.rn.f32x2 %0, %1, %2, %3;" : "=l"(d) : "l"(a), "l"(b), "l"(c));
    return d;
}
__device__ __forceinline__ ull pk(float x, float y) {
    ull r;
    asm("mov.b64 %0, {%1,%2};" : "=l"(r) : "f"(x), "f"(y));
    return r;
}
__device__ __forceinline__ float2 upk(ull v) {
    float2 r;
    asm("mov.b64 {%0,%1}, %2;" : "=f"(r.x), "=f"(r.y) : "l"(v));
    return r;
}
__device__ __forceinline__ void red4(float* p, float4 m) {
    asm volatile("red.global.add.v4.f32 [%0], {%1,%2,%3,%4};"
                 :: "l"(p), "f"(m.x), "f"(m.y), "f"(m.z), "f"(m.w) : "memory");
}

// ---------------- zero scratch ------------------------------------------------
__global__ void zero_kernel() {
    int t = blockIdx.x * blockDim.x + threadIdx.x;
    int stride = gridDim.x * blockDim.x;
    float4 z = {0.f, 0.f, 0.f, 0.f};
    for (int i = t; i < N_NODES * DIM / 4; i += stride) ((float4*)g_agg)[i] = z;
    for (int i = t; i < N_GRAPHS * DIM / 4; i += stride) ((float4*)g_pool)[i] = z;
}

// ---------------- edge kernel -------------------------------------------------
// agg[dst] += relu(x[src] + We @ ea + be).  16 lanes per edge, 4 features each.
// We register-cached (8 ull = 16 floats per feature), k packed for FFMA2.
__global__ void __launch_bounds__(256) edge_kernel(
    int xsel, const float* __restrict__ xext,
    const float* __restrict__ ea,
    const int* __restrict__ src, const int* __restrict__ dst,
    const float* __restrict__ We, const float* __restrict__ be)
{
    const float* xin = (xsel == 0) ? xext : (xsel == 1) ? g_h1 : g_h2;
    int t = blockIdx.x * blockDim.x + threadIdx.x;
    int fq = t & 15;
    int f0 = fq * 4;
    int e0 = t >> 4;
    int estep = (gridDim.x * blockDim.x) >> 4;

    ull w[4][8];
    #pragma unroll
    for (int i = 0; i < 4; i++) {
        const ull* wr = (const ull*)(We + (f0 + i) * 16);
        #pragma unroll
        for (int p = 0; p < 8; p++) w[i][p] = __ldg(wr + p);
    }
    ull accInit[4];
    #pragma unroll
    for (int i = 0; i < 4; i++) accInit[i] = pk(__ldg(be + f0 + i), 0.f);

    for (int e = e0; e < N_EDGES; e += estep) {
        int s = __ldg(src + e);
        int d = __ldg(dst + e);
        const ulonglong2* eau = (const ulonglong2*)(ea + (size_t)e * 16);
        ulonglong2 p0 = eau[0], p1 = eau[1], p2 = eau[2], p3 = eau[3];
        ull b[8] = {p0.x, p0.y, p1.x, p1.y, p2.x, p2.y, p3.x, p3.y};

        float ev[4];
        #pragma unroll
        for (int i = 0; i < 4; i++) {
            ull acc = accInit[i];
            #pragma unroll
            for (int p = 0; p < 8; p++) acc = ffma2(w[i][p], b[p], acc);
            float2 u = upk(acc);
            ev[i] = u.x + u.y;
        }
        float4 xr = *(const float4*)(xin + (size_t)s * DIM + f0);
        float4 m;
        m.x = fmaxf(xr.x + ev[0], 0.f);
        m.y = fmaxf(xr.y + ev[1], 0.f);
        m.z = fmaxf(xr.z + ev[2], 0.f);
        m.w = fmaxf(xr.w + ev[3], 0.f);
        red4(g_agg + (size_t)d * DIM + f0, m);
    }
}

// ---------------- node kernel -------------------------------------------------
// hout = lrelu(BN((x + agg) @ W^T + b)); also re-zeroes agg for the next layer.
// W row register-cached (32 ull), k packed for FFMA2. 4 nodes per 256-thr block iter.
__global__ void __launch_bounds__(256) node_kernel(
    int xsel, const float* __restrict__ xext,
    const float* __restrict__ W, const float* __restrict__ b,
    const float* __restrict__ g, const float* __restrict__ bt,
    const float* __restrict__ mean, const float* __restrict__ var,
    int osel)
{
    const float* xin = (xsel == 0) ? xext : (xsel == 1) ? g_h1 : g_h2;
    float* hout = (osel == 1) ? g_h1 : (osel == 2) ? g_h2 : g_h3;

    __shared__ __align__(16) float ys[4][64];
    int tid = threadIdx.x;
    int f = tid & 63, slot = tid >> 6;

    ull w[32];
    const ull* wr = (const ull*)(W + f * 64);
    #pragma unroll
    for (int p = 0; p < 32; p++) w[p] = __ldg(wr + p);
    float bias = __ldg(b + f);
    float sc = __ldg(g + f) * rsqrtf(__ldg(var + f) + BN_EPS);
    float sh = __ldg(bt + f) - __ldg(mean + f) * sc;

    for (int base = blockIdx.x * 4; base < N_NODES; base += gridDim.x * 4) {
        int n = base + slot;
        size_t off = (size_t)n * 64 + f;
        ys[slot][f] = xin[off] + g_agg[off];
        g_agg[off] = 0.f;   // pre-zero agg for next layer's scatter
        __syncthreads();
        const ulonglong2* yu = (const ulonglong2*)ys[slot];
        ull acc = pk(bias, 0.f);
        #pragma unroll
        for (int p = 0; p < 16; p++) {
            ulonglong2 y = yu[p];
            acc = ffma2(w[2 * p], y.x, acc);
            acc = ffma2(w[2 * p + 1], y.y, acc);
        }
        float2 u = upk(acc);
        float z = (u.x + u.y) * sc + sh;
        hout[off] = (z >= 0.f) ? z : NEG * z;
        __syncthreads();
    }
}

// ---------------- pool kernel -------------------------------------------------
__global__ void pool_kernel(const int* __restrict__ batch) {
    int t = blockIdx.x * blockDim.x + threadIdx.x;
    if (t >= N_NODES * 16) return;
    int n = t >> 4, q = t & 15;
    float4 v = *(const float4*)(g_h3 + (size_t)n * 64 + q * 4);
    int gi = __ldg(batch + n);
    red4(g_pool + (size_t)gi * 64 + q * 4, v);
}

// ---------------- final MLP kernel -------------------------------------------
// out[n] = Wl2 . lrelu(Wl1 @ [h1|h2|h3|pool[batch[n]]] + bl1) + bl2
// 512 thr/block, 64 nodes/block. Wl1 staged per-64-k-chunk in smem ([256][68] padded),
// v-chunk is exactly one of the four source arrays (no concat staging needed).
// Per thread: 4 features x 8 nodes register tile, k packed for FFMA2.
#define WS_PAD 68
#define FINAL_SMEM ((256 * WS_PAD + 64 * 64) * 4)

__global__ void __launch_bounds__(512) final_kernel(
    const int* __restrict__ batch,
    const float* __restrict__ Wl1, const float* __restrict__ bl1,
    const float* __restrict__ Wl2, const float* __restrict__ bl2,
    float* __restrict__ out)
{
    extern __shared__ float smem[];
    float* Ws = smem;                 // [256][WS_PAD]
    float* vs = smem + 256 * WS_PAD;  // [64][64]

    int tid = threadIdx.x;
    int ft = tid & 31;
    int w = tid >> 5;
    int ng = w & 7;     // node group (8 nodes)
    int fh = w >> 3;    // feature half (0: 0..127, 1: 128..255)
    int nodeBase = blockIdx.x * 64;

    ull acc[4][8];
    #pragma unroll
    for (int i = 0; i < 4; i++) {
        float bb = __ldg(bl1 + fh * 128 + ft + 32 * i);
        #pragma unroll
        for (int m = 0; m < 8; m++) acc[i][m] = pk(bb, 0.f);
    }

    for (int c = 0; c < 4; c++) {
        __syncthreads();
        // stage Wl1 chunk (cols c*64 .. c*64+63), row-major into padded smem
        {
            int j = tid >> 1, half = tid & 1;
            const float4* srcw = (const float4*)(Wl1 + (size_t)j * 256 + c * 64 + half * 32);
            float4* dstw = (float4*)(Ws + j * WS_PAD + half * 32);
            #pragma unroll
            for (int q = 0; q < 8; q++) dstw[q] = __ldg(srcw + q);
        }
        // stage v chunk: h1 / h2 / h3 / pool[batch]
        {
            const float* srcArr = (c == 0) ? g_h1 : (c == 1) ? g_h2 : (c == 2) ? g_h3 : g_pool;
            #pragma unroll
            for (int r = 0; r < 2; r++) {
                int idx = tid + 512 * r;
                int n = idx >> 4, k4 = idx & 15;
                int gn = nodeBase + n;
                float4 v = {0.f, 0.f, 0.f, 0.f};
                if (gn < N_NODES) {
                    size_t row = (c == 3) ? (size_t)__ldg(batch + gn) * 64 : (size_t)gn * 64;
                    v = *(const float4*)(srcArr + row + k4 * 4);
                }
                *(float4*)(vs + n * 64 + k4 * 4) = v;
            }
        }
        __syncthreads();

        const ulonglong2* Wsu2 = (const ulonglong2*)Ws;
        const ulonglong2* vsu2 = (const ulonglong2*)vs;
        #pragma unroll 4
        for (int kp2 = 0; kp2 < 16; kp2++) {
            ulonglong2 a[4];
            #pragma unroll
            for (int i = 0; i < 4; i++) {
                int f = fh * 128 + ft + 32 * i;
                a[i] = Wsu2[f * (WS_PAD / 4) + kp2];   // WS_PAD floats = WS_PAD/4 ull2
            }
            #pragma unroll
            for (int m = 0; m < 8; m++) {
                ulonglong2 bv = vsu2[(ng * 8 + m) * 16 + kp2];
                #pragma unroll
                for (int i = 0; i < 4; i++) {
                    acc[i][m] = ffma2(a[i].x, bv.x, acc[i][m]);
                    acc[i][m] = ffma2(a[i].y, bv.y, acc[i][m]);
                }
            }
        }
    }

    // epilogue: lrelu + dot with Wl2, reduce across lanes and feature halves
    float wl2v[4];
    #pragma unroll
    for (int i = 0; i < 4; i++) wl2v[i] = __ldg(Wl2 + fh * 128 + ft + 32 * i);

    float po[8];
    #pragma unroll
    for (int m = 0; m < 8; m++) {
        float sum = 0.f;
        #pragma unroll
        for (int i = 0; i < 4; i++) {
            float2 u = upk(acc[i][m]);
            float zv = u.x + u.y;
            zv = (zv >= 0.f) ? zv : NEG * zv;
            sum += zv * wl2v[i];
        }
        po[m] = sum;
    }
    #pragma unroll
    for (int m = 0; m < 8; m++) {
        #pragma unroll
        for (int o = 16; o > 0; o >>= 1) po[m] += __shfl_xor_sync(0xffffffffu, po[m], o);
    }

    __shared__ float red[2][8][8];
    if (ft < 8) red[fh][ng][ft] = po[ft];
    __syncthreads();
    if (fh == 0 && ft < 8) {
        int gn = nodeBase + ng * 8 + ft;
        if (gn < N_NODES) out[gn] = red[0][ng][ft] + red[1][ng][ft] + bl2[0];
    }
}

// ---------------- launch ------------------------------------------------------
extern "C" void kernel_launch(void* const* d_in, const int* in_sizes, int n_in,
                              void* d_out, int out_size)
{
    const float* x     = (const float*)d_in[0];
    const int*   ei    = (const int*)d_in[1];
    const float* ea    = (const float*)d_in[2];
    const int*   batch = (const int*)d_in[3];

    const float* We[3] = {(const float*)d_in[4],  (const float*)d_in[12], (const float*)d_in[20]};
    const float* be[3] = {(const float*)d_in[5],  (const float*)d_in[13], (const float*)d_in[21]};
    const float* W[3]  = {(const float*)d_in[6],  (const float*)d_in[14], (const float*)d_in[22]};
    const float* b[3]  = {(const float*)d_in[7],  (const float*)d_in[15], (const float*)d_in[23]};
    const float* g[3]  = {(const float*)d_in[8],  (const float*)d_in[16], (const float*)d_in[24]};
    const float* bt[3] = {(const float*)d_in[9],  (const float*)d_in[17], (const float*)d_in[25]};
    const float* mn[3] = {(const float*)d_in[10], (const float*)d_in[18], (const float*)d_in[26]};
    const float* vr[3] = {(const float*)d_in[11], (const float*)d_in[19], (const float*)d_in[27]};
    const float* Wl1 = (const float*)d_in[28];
    const float* bl1 = (const float*)d_in[29];
    const float* Wl2 = (const float*)d_in[30];
    const float* bl2 = (const float*)d_in[31];
    float* out = (float*)d_out;

    const int* src = ei;
    const int* dst = ei + N_EDGES;

    cudaFuncSetAttribute(final_kernel, cudaFuncAttributeMaxDynamicSharedMemorySize, FINAL_SMEM);

    zero_kernel<<<2048, 256>>>();

    for (int l = 0; l < 3; l++) {
        edge_kernel<<<592, 256>>>(l, x, ea, src, dst, We[l], be[l]);
        node_kernel<<<1024, 256>>>(l, x, W[l], b[l], g[l], bt[l], mn[l], vr[l], l + 1);
    }

    pool_kernel<<<(N_NODES * 16 + 255) / 256, 256>>>(batch);

    final_kernel<<<(N_NODES + 63) / 64, 512, FINAL_SMEM>>>(batch, Wl1, bl1, Wl2, bl2, out);
}